// round 13
// baseline (speedup 1.0000x reference)
#include <cuda_runtime.h>

// Lifting wavelet v13: SINGLE kernel, barrier-free. Shuffle-halo window (v10)
// + SHUFFLE-BROADCAST taps: lane j of each warp holds tap j in ONE register
// (lanes 0-7 wavelet, lanes 8-15 scaling); the conv loop reads taps via
// __shfl_sync. No smem, no __syncthreads, no setup graph node, no pinned
// tap registers -> v10's 38.7us kernel body at v7's single-node overhead.
// input: (4096, 8192) f32. even = in[:, ::2], odd = in[:, 1::2] (4096 each).
// wavelet[j] = scaling_rec[7-j] * (j odd ? -1 : +1)
// odd_out[k]  = odd[k]  - sum_j wavelet[j] * even[(k-j) mod 4096]
// even_out[k] = even[k] - sum_j scaling[j] * odd[(k-j) mod 4096]
// Output: [even_updated | odd_updated], each 4096x4096 f32.

#define ROWS    4096
#define ROWLEN  8192
#define HALF    4096
#define NTH     256
#define FMASK   (ROWLEN - 1)
#define FULL    0xffffffffu

__global__ __launch_bounds__(NTH, 6)   // <=42 regs
void wavelet_fwd_v13(const float* __restrict__ in,
                     const float* __restrict__ scaling,
                     const float* __restrict__ scaling_rec,
                     float* __restrict__ out)
{
    const int g    = blockIdx.x * NTH + threadIdx.x;  // 0 .. 4M-1
    const int row  = g >> 10;                          // 1024 threads per row
    const int lk   = (g & 1023) << 2;                  // pair base: 0..4092
    const int lane = threadIdx.x & 31;

    const float* rowp = in + (size_t)row * ROWLEN;

    // One-register tap bank: lane j (0-7) holds wavelet[j]; lane 8+j holds
    // scaling[j]; lanes 16-31 hold don't-care copies.
    float tapv;
    {
        int t = lane & 7;
        float w  = scaling_rec[7 - t];
        float wav = (t & 1) ? -w : w;       // wavelet[t]
        float scl = scaling[t];
        tapv = (lane & 8) ? scl : wav;
    }

    // wnd[j] = row[(2lk-16+j) mod 8192], j = 0..23.
    float wnd[24];

    // Own 8 floats: row[2lk .. 2lk+7] -> wnd[16..23]. Amplification 1.0x.
    {
        const float4* p = reinterpret_cast<const float4*>(rowp + 2 * lk);
        float4 v0 = p[0];
        float4 v1 = p[1];
        wnd[16] = v0.x; wnd[17] = v0.y; wnd[18] = v0.z; wnd[19] = v0.w;
        wnd[20] = v1.x; wnd[21] = v1.y; wnd[22] = v1.z; wnd[23] = v1.w;
    }

    // Halo via shuffles (consecutive lanes own consecutive 4-pair segments;
    // blocks never span rows):
    //   lane-1 owns row[2lk-8 .. 2lk-1]  -> wnd[8..15]
    //   lane-2 owns row[2lk-16 .. 2lk-9] -> wnd[0..7]
#pragma unroll
    for (int i = 0; i < 8; i++) {
        wnd[8 + i] = __shfl_up_sync(FULL, wnd[16 + i], 1);
        wnd[i]     = __shfl_up_sync(FULL, wnd[16 + i], 2);
    }

    // Lanes 0,1 fix up what shuffles couldn't provide (circular via & FMASK).
    if (lane < 2) {
#pragma unroll
        for (int q = 0; q < 2; q++) {
            int fi = (2 * lk - 16 + 4 * q) & FMASK;
            float4 v = *reinterpret_cast<const float4*>(rowp + fi);
            wnd[4*q+0] = v.x; wnd[4*q+1] = v.y; wnd[4*q+2] = v.z; wnd[4*q+3] = v.w;
        }
        if (lane == 0) {
#pragma unroll
            for (int q = 0; q < 2; q++) {
                int fi = (2 * lk - 8 + 4 * q) & FMASK;
                float4 v = *reinterpret_cast<const float4*>(rowp + fi);
                wnd[8+4*q+0] = v.x; wnd[8+4*q+1] = v.y;
                wnd[8+4*q+2] = v.z; wnd[8+4*q+3] = v.w;
            }
        }
    }

    const size_t obase = (size_t)row * HALF + lk;

    // --- Odd outputs: rO[m] = wnd[2m+17] - sum_j wavelet[j]*wnd[2m+16-2j] ---
    {
        float a0 = wnd[17], a1 = wnd[19], a2 = wnd[21], a3 = wnd[23];
#pragma unroll
        for (int j = 0; j < 8; j++) {
            float wj = __shfl_sync(FULL, tapv, j);   // tap j, short live range
            a0 -= wj * wnd[16 - 2*j];
            a1 -= wj * wnd[18 - 2*j];
            a2 -= wj * wnd[20 - 2*j];
            a3 -= wj * wnd[22 - 2*j];
        }
        *reinterpret_cast<float4*>(out + (size_t)ROWS * HALF + obase) =
            make_float4(a0, a1, a2, a3);
    }

    // --- Even outputs: rE[m] = wnd[2m+16] - sum_j scaling[j]*wnd[2m+17-2j] ---
    {
        float e0 = wnd[16], e1 = wnd[18], e2 = wnd[20], e3 = wnd[22];
#pragma unroll
        for (int j = 0; j < 8; j++) {
            float cj = __shfl_sync(FULL, tapv, 8 + j);
            e0 -= cj * wnd[17 - 2*j];
            e1 -= cj * wnd[19 - 2*j];
            e2 -= cj * wnd[21 - 2*j];
            e3 -= cj * wnd[23 - 2*j];
        }
        *reinterpret_cast<float4*>(out + obase) =
            make_float4(e0, e1, e2, e3);
    }
}

extern "C" void kernel_launch(void* const* d_in, const int* in_sizes, int n_in,
                              void* d_out, int out_size)
{
    const float* input       = (const float*)d_in[0];
    const float* scaling     = (const float*)d_in[1];
    const float* scaling_rec = (const float*)d_in[2];
    float* out = (float*)d_out;

    const int total_threads = ROWS * (HALF / 4);       // 4M
    wavelet_fwd_v13<<<total_threads / NTH, NTH>>>(input, scaling, scaling_rec, out);
}

// round 14
// speedup vs baseline: 1.0262x; 1.0262x over previous
#include <cuda_runtime.h>

// Lifting wavelet v14: v8 body (LDC taps -> uniform regs, 32 regs, occ 84%,
// kernel 38.8us) with the setup-node cost hidden via Programmatic Dependent
// Launch: the main kernel is launched with programmatic stream serialization,
// overlapping its launch/window-load phase with the tiny tap-setup kernel;
// cudaGridDependencySynchronize() gates the first LDC of the taps.
// Rationale (R13 finding): constant taps are structurally unique — LDCU puts
// them in uniform registers (no thread-reg pinning) on the constant port (no
// L1tex wavefronts). Every other tap mechanism (LDG/LDS/SHFL) lost 4-6us.
// input: (4096, 8192) f32. even = in[:, ::2], odd = in[:, 1::2] (4096 each).
// wavelet[j] = scaling_rec[7-j] * (j odd ? -1 : +1)
// odd_out[k]  = odd[k]  - sum_j wavelet[j] * even[(k-j) mod 4096]
// even_out[k] = even[k] - sum_j scaling[j] * odd[(k-j) mod 4096]
// Output: [even_updated | odd_updated], each 4096x4096 f32.

#define ROWS    4096
#define ROWLEN  8192
#define HALF    4096
#define NTH     256
#define FMASK   (ROWLEN - 1)

// [0..7] = wavelet taps (reversed + sign-flipped), [8..15] = scaling taps.
__constant__ float cTaps[16];

__global__ void wavelet_setup(const float* __restrict__ scaling,
                              const float* __restrict__ scaling_rec,
                              float* __restrict__ taps_dst)
{
    int t = threadIdx.x;
    if (t < 8) {
        float w = scaling_rec[7 - t];
        taps_dst[t]     = (t & 1) ? -w : w;   // wavelet[j]
        taps_dst[8 + t] = scaling[t];
    }
}

__global__ __launch_bounds__(NTH)
void wavelet_fwd_v14(const float* __restrict__ in,
                     float* __restrict__ out)
{
    const int g   = blockIdx.x * NTH + threadIdx.x;  // 0 .. 4M-1
    const int row = g >> 10;                          // 1024 threads per row
    const int lk  = (g & 1023) << 2;                  // pair base: 0..4092

    const float* rowp = in + (size_t)row * ROWLEN;

    // Window: input floats (2*lk - 16 + i) mod 8192, i = 0..23.
    // 6 aligned float4 loads, circular via & FMASK. Front-batched -> MLP=6.
    // Issued BEFORE the dependency sync so they overlap the setup kernel.
    float wnd[24];
#pragma unroll
    for (int q = 0; q < 6; q++) {
        int fi = (2 * lk - 16 + 4 * q) & FMASK;
        float4 v = *reinterpret_cast<const float4*>(rowp + fi);
        wnd[4*q+0] = v.x; wnd[4*q+1] = v.y; wnd[4*q+2] = v.z; wnd[4*q+3] = v.w;
    }

    // Wait for the setup kernel's tap writes (PDL). Const L1 is cold at this
    // kernel's launch, so the LDCs below miss to L2 and see fresh values.
    cudaGridDependencySynchronize();

    // Taps via LDC: uniform registers, constant port, rematerializable.
    const float w0 = cTaps[0], w1 = cTaps[1], w2 = cTaps[2], w3 = cTaps[3];
    const float w4 = cTaps[4], w5 = cTaps[5], w6 = cTaps[6], w7 = cTaps[7];
    const float c0 = cTaps[8],  c1 = cTaps[9],  c2 = cTaps[10], c3 = cTaps[11];
    const float c4 = cTaps[12], c5 = cTaps[13], c6 = cTaps[14], c7 = cTaps[15];

    // Pair (lk+m): even = wnd[2m+16], odd = wnd[2m+17].
    float rE[4], rO[4];
#pragma unroll
    for (int m = 0; m < 4; m++) {
        const int b = 2 * m + 16;
        float e8 = wnd[b], o8 = wnd[b + 1];
        float ce = w0*e8
                 + w1*wnd[b-2]  + w2*wnd[b-4]  + w3*wnd[b-6]
                 + w4*wnd[b-8]  + w5*wnd[b-10] + w6*wnd[b-12]
                 + w7*wnd[b-14];
        float co = c0*o8
                 + c1*wnd[b-1]  + c2*wnd[b-3]  + c3*wnd[b-5]
                 + c4*wnd[b-7]  + c5*wnd[b-9]  + c6*wnd[b-11]
                 + c7*wnd[b-13];
        rO[m] = o8 - ce;   // odd  - conv(even, wavelet)
        rE[m] = e8 - co;   // even - conv(odd,  scaling)
    }

    const size_t obase = (size_t)row * HALF + lk;
    *reinterpret_cast<float4*>(out + obase) =
        make_float4(rE[0], rE[1], rE[2], rE[3]);
    *reinterpret_cast<float4*>(out + (size_t)ROWS * HALF + obase) =
        make_float4(rO[0], rO[1], rO[2], rO[3]);
}

extern "C" void kernel_launch(void* const* d_in, const int* in_sizes, int n_in,
                              void* d_out, int out_size)
{
    const float* input       = (const float*)d_in[0];
    const float* scaling     = (const float*)d_in[1];
    const float* scaling_rec = (const float*)d_in[2];
    float* out = (float*)d_out;

    // Device address of the __constant__ symbol (host query; no allocation).
    float* taps_dst = nullptr;
    cudaGetSymbolAddress((void**)&taps_dst, cTaps);

    wavelet_setup<<<1, 32>>>(scaling, scaling_rec, taps_dst);

    // Main kernel with Programmatic Dependent Launch: launch overlaps the
    // setup kernel; the in-kernel cudaGridDependencySynchronize() provides
    // the ordering on the tap values.
    const int total_threads = ROWS * (HALF / 4);       // 4M
    cudaLaunchConfig_t cfg = {};
    cfg.gridDim  = dim3(total_threads / NTH);
    cfg.blockDim = dim3(NTH);
    cfg.dynamicSmemBytes = 0;
    cfg.stream = 0;
    cudaLaunchAttribute attrs[1];
    attrs[0].id = cudaLaunchAttributeProgrammaticStreamSerialization;
    attrs[0].val.programmaticStreamSerializationAllowed = 1;
    cfg.attrs = attrs;
    cfg.numAttrs = 1;
    cudaLaunchKernelEx(&cfg, wavelet_fwd_v14, input, out);
}